// round 7
// baseline (speedup 1.0000x reference)
#include <cuda_runtime.h>

#define TPB 128
#define EPSV 1e-5f

__device__ __forceinline__ float fast_tanh(float x) {
    float r;
    asm("tanh.approx.f32 %0, %1;" : "=f"(r) : "f"(x));
    return r;
}
__device__ __forceinline__ float fast_silu(float z) {
    return z * (0.5f * fast_tanh(0.5f * z) + 0.5f);
}

// Block-resident GridNet step: dual-batch interleaved, 3 CTAs/SM,
// batches A/B packed as float2 in ONE smem buffer -> window rows load as
// 16B-aligned LDS.128 serving both batches (48 LDS.64 -> 24 LDS.128/iter),
// write-back as STS.64 pairs. Row stride 12 float2 keeps alignment and a
// conflict-free 4-bank-group pattern. Rolling-row FMA keeps regs <= 170.
__global__ __launch_bounds__(TPB, 3)
void gridnet_kernel(const float* __restrict__ W,
                    const float* __restrict__ Bias,
                    const float* __restrict__ Rscale,
                    const float* __restrict__ X,
                    float* __restrict__ Y)
{
    // [10 planes][10 rows][12 f2-slots] ; only slots 0..9 used per row
    __shared__ __align__(16) float2 s0[1200];
    __shared__ __align__(16) float2 s1[1200];
    __shared__ float red[2][16];   // [parity][batch*8 + warp*2 + {S,S2}]

    const int t    = threadIdx.x;
    const int k2   = t & 3;
    const int j2   = (t >> 2) & 3;
    const int ii   = t >> 4;           // 0..7
    const int lane = t & 31;
    const int wid  = t >> 5;

    const int sb = blockIdx.x >> 2;    // spatial block 0..511
    const int bg = blockIdx.x & 3;     // batch group 0..3
    const int bk = sb & 7, bn = (sb >> 3) & 7, bm = sb >> 6;

    const int gi  = bm * 8 + ii;
    const int gj0 = bn * 8 + 2 * j2;
    const int gk0 = bk * 8 + 2 * k2;
    const int jb  = 2 * j2;
    const int kb2 = 2 * k2;            // f2 index of window start in k

    // ---- weights, sum-of-weights, bias, residual scale into registers ----
    float w[27][2][2];
    float sumw[2][2] = {{0.f, 0.f}, {0.f, 0.f}};
#pragma unroll
    for (int tap = 0; tap < 27; ++tap) {
#pragma unroll
        for (int jj = 0; jj < 2; ++jj) {
            const float2 wv = *reinterpret_cast<const float2*>(
                W + (((size_t)tap * 64 + gi) * 64 + (gj0 + jj)) * 64 + gk0);
            w[tap][jj][0] = wv.x; w[tap][jj][1] = wv.y;
            sumw[jj][0] += wv.x;  sumw[jj][1] += wv.y;
        }
    }
    float bbv[2][2], rsv[2][2];
#pragma unroll
    for (int jj = 0; jj < 2; ++jj) {
        const float2 bv = *reinterpret_cast<const float2*>(
            Bias + ((size_t)gi * 64 + gj0 + jj) * 64 + gk0);
        const float2 rv = *reinterpret_cast<const float2*>(
            Rscale + ((size_t)gi * 64 + gj0 + jj) * 64 + gk0);
        bbv[jj][0] = bv.x; bbv[jj][1] = bv.y;
        rsv[jj][0] = rv.x; rsv[jj][1] = rv.y;
    }

    // f2 offset of this thread's first output (jj=0, kk=0)
    const int curoff = (ii + 1) * 120 + (jb + 1) * 12 + (kb2 + 1);

#pragma unroll 1
    for (int pass = 0; pass < 2; ++pass) {
        const int ba  = bg * 4 + pass * 2;      // batch A
        const int bbi = ba + 1;                 // batch B
        const float* Xa = X + (size_t)ba  * 262144;
        const float* Xb = X + (size_t)bbi * 262144;

        // ---- load both padded blocks (interleaved), fold initial sums ----
        float Sa = 0.f, S2a = 0.f, Sb = 0.f, S2b = 0.f;
        for (int n = t; n < 1000; n += TPB) {
            const int a = n / 100;
            const int r = n - a * 100;
            const int q = r / 10;
            const int c = r - q * 10;
            const int gm = bm * 8 + a - 1;
            const int gn = bn * 8 + q - 1;
            const int gq = bk * 8 + c - 1;
            float va = 0.f, vb = 0.f;
            if ((unsigned)gm < 64u && (unsigned)gn < 64u && (unsigned)gq < 64u) {
                const size_t gidx = ((size_t)gm * 64 + gn) * 64 + gq;
                va = Xa[gidx];
                vb = Xb[gidx];
            }
            const int off = a * 120 + q * 12 + c;
            const float2 v2 = make_float2(va, vb);
            s0[off] = v2;
            // second buffer only needs the constant halo (inner rewritten at it=0)
            if (a == 0 || a == 9 || q == 0 || q == 9 || c == 0 || c == 9)
                s1[off] = v2;
            Sa += va; S2a += va * va;
            Sb += vb; S2b += vb * vb;
        }
#pragma unroll
        for (int o = 16; o; o >>= 1) {
            Sa  += __shfl_xor_sync(0xffffffffu, Sa,  o);
            S2a += __shfl_xor_sync(0xffffffffu, S2a, o);
            Sb  += __shfl_xor_sync(0xffffffffu, Sb,  o);
            S2b += __shfl_xor_sync(0xffffffffu, S2b, o);
        }
        if (lane == 0) {
            red[1][wid * 2]     = Sa; red[1][wid * 2 + 1]     = S2a;
            red[1][8 + wid * 2] = Sb; red[1][8 + wid * 2 + 1] = S2b;
        }
        __syncthreads();

        // current inner values for this thread's 4 outputs, each batch
        float ca[2][2], cb[2][2];
#pragma unroll
        for (int jj = 0; jj < 2; ++jj)
#pragma unroll
            for (int kk = 0; kk < 2; ++kk) {
                const float2 c2 = s0[curoff + jj * 12 + kk];
                ca[jj][kk] = c2.x;
                cb[jj][kk] = c2.y;
            }

        Sa = 0.f; S2a = 0.f; Sb = 0.f; S2b = 0.f;   // running totals

#pragma unroll 2
        for (int it = 0; it < 8; ++it) {
            const float2* rd = (it & 1) ? s1 : s0;
            float2*       wr = (it & 1) ? s0 : s1;
            const int     pb = (it + 1) & 1;

            // cross-warp partial loads issued early (hidden by FMA block)
            const float dSaS  = (red[pb][0] + red[pb][2]) + (red[pb][4] + red[pb][6]);
            const float dS2aS = (red[pb][1] + red[pb][3]) + (red[pb][5] + red[pb][7]);
            const float dSbS  = (red[pb][8]  + red[pb][10]) + (red[pb][12] + red[pb][14]);
            const float dS2bS = (red[pb][9]  + red[pb][11]) + (red[pb][13] + red[pb][15]);

            float aa[2][2] = {{0.f, 0.f}, {0.f, 0.f}};
            float ab[2][2] = {{0.f, 0.f}, {0.f, 0.f}};
#pragma unroll
            for (int dx = 0; dx < 3; ++dx) {
                const float2* rp = rd + (ii + dx) * 120 + jb * 12 + kb2;
#pragma unroll
                for (int r = 0; r < 4; ++r) {
                    // one row: 4 k-positions x 2 batches via 2x LDS.128
                    const float4 q0 = *reinterpret_cast<const float4*>(rp + r * 12);
                    const float4 q1 = *reinterpret_cast<const float4*>(rp + r * 12 + 2);
                    float va[4], vb[4];
                    va[0] = q0.x; vb[0] = q0.y; va[1] = q0.z; vb[1] = q0.w;
                    va[2] = q1.x; vb[2] = q1.y; va[3] = q1.z; vb[3] = q1.w;
                    // row r feeds (dy,jj) with dy + jj == r
#pragma unroll
                    for (int dy = 0; dy < 3; ++dy) {
#pragma unroll
                        for (int jj = 0; jj < 2; ++jj) {
                            if (dy + jj == r) {
#pragma unroll
                                for (int dz = 0; dz < 3; ++dz) {
                                    const int tap = dx * 9 + dy * 3 + dz;
                                    aa[jj][0] = fmaf(va[dz],     w[tap][jj][0], aa[jj][0]);
                                    aa[jj][1] = fmaf(va[dz + 1], w[tap][jj][1], aa[jj][1]);
                                    ab[jj][0] = fmaf(vb[dz],     w[tap][jj][0], ab[jj][0]);
                                    ab[jj][1] = fmaf(vb[dz + 1], w[tap][jj][1], ab[jj][1]);
                                }
                            }
                        }
                    }
                }
            }

            // fold deferred partials; per-batch stats
            Sa += dSaS; S2a += dS2aS;
            Sb += dSbS; S2b += dS2bS;
            const float ma  = Sa * (1.0f / 1000.0f);
            const float ra  = rsqrtf(S2a * (1.0f / 1000.0f) - ma * ma + EPSV);
            const float mb  = Sb * (1.0f / 1000.0f);
            const float rb2 = rsqrtf(S2b * (1.0f / 1000.0f) - mb * mb + EPSV);

            // epilogue both batches; paired STS.64 stores before the reduction
            float dSa = 0.f, dS2a = 0.f, dSb = 0.f, dS2b = 0.f;
#pragma unroll
            for (int jj = 0; jj < 2; ++jj)
#pragma unroll
                for (int kk = 0; kk < 2; ++kk) {
                    const float za = fmaf(-ma, sumw[jj][kk], aa[jj][kk]) * ra + bbv[jj][kk];
                    const float na = fmaf(rsv[jj][kk], fast_silu(za), ca[jj][kk]);
                    const float zb = fmaf(-mb, sumw[jj][kk], ab[jj][kk]) * rb2 + bbv[jj][kk];
                    const float nb = fmaf(rsv[jj][kk], fast_silu(zb), cb[jj][kk]);
                    wr[curoff + jj * 12 + kk] = make_float2(na, nb);
                    dSa  += na - ca[jj][kk];
                    dS2a += fmaf(na, na, -ca[jj][kk] * ca[jj][kk]);
                    ca[jj][kk] = na;
                    dSb  += nb - cb[jj][kk];
                    dS2b += fmaf(nb, nb, -cb[jj][kk] * cb[jj][kk]);
                    cb[jj][kk] = nb;
                }

            // four independent butterfly chains — pipeline through shfl
#pragma unroll
            for (int o = 16; o; o >>= 1) {
                dSa  += __shfl_xor_sync(0xffffffffu, dSa,  o);
                dS2a += __shfl_xor_sync(0xffffffffu, dS2a, o);
                dSb  += __shfl_xor_sync(0xffffffffu, dSb,  o);
                dS2b += __shfl_xor_sync(0xffffffffu, dS2b, o);
            }
            const int rbp = it & 1;
            if (lane == 0) {
                red[rbp][wid * 2]     = dSa; red[rbp][wid * 2 + 1]     = dS2a;
                red[rbp][8 + wid * 2] = dSb; red[rbp][8 + wid * 2 + 1] = dS2b;
            }
            __syncthreads();
        }

        // ---- write final outputs for both batches ----
        float* Ya = Y + (size_t)ba  * 262144;
        float* Yb = Y + (size_t)bbi * 262144;
#pragma unroll
        for (int jj = 0; jj < 2; ++jj) {
            const size_t o = ((size_t)gi * 64 + gj0 + jj) * 64 + gk0;
            float2 oa; oa.x = ca[jj][0]; oa.y = ca[jj][1];
            float2 ob; ob.x = cb[jj][0]; ob.y = cb[jj][1];
            *reinterpret_cast<float2*>(Ya + o) = oa;
            *reinterpret_cast<float2*>(Yb + o) = ob;
        }
        // it=7 barrier already ordered all SMEM reads before next pass's loads.
    }
}

extern "C" void kernel_launch(void* const* d_in, const int* in_sizes, int n_in,
                              void* d_out, int out_size)
{
    const float* W  = (const float*)d_in[0];   // (27,64,64,64)
    const float* Bb = (const float*)d_in[1];   // (64,64,64)
    const float* Rs = (const float*)d_in[2];   // (64,64,64)
    const float* X  = (const float*)d_in[3];   // (16,64,64,64)
    float* Y = (float*)d_out;

    gridnet_kernel<<<2048, TPB>>>(W, Bb, Rs, X, Y);
}